// round 4
// baseline (speedup 1.0000x reference)
#include <cuda_runtime.h>
#include <cstdint>

#define NT 1024
#define NH 2048
#define NI 2048
#define NEXP 16
#define NTOP 4
#define NSLOT (NT*NTOP)
#define NBLKS 64
#define ALPHA 1.702f
#define FLIMIT 7.0f
#define NCHUNK 64            // K chunks of 32 floats

#define STRW 36              // padded words per smem row (32 data + 4 pad)
#define STRB 144             // bytes per row
#define A_WORDS (256*STRW)               // 9216
#define STAGE_WORDS (A_WORDS + 128*STRW) // 13824 words = 55296 B
#define DSMEM_BYTES (2*STAGE_WORDS*4)    // 110592

// ---------------- scratch ----------------
__device__ int   g_tok_exp[NSLOT];
__device__ float g_tok_w[NSLOT];
__device__ int   g_counts[NEXP];
__device__ int   g_offsets[NEXP];
__device__ int   g_token_list[NSLOT];
__device__ int   g_slot_of[NSLOT];
__device__ float g_xr[(size_t)NT * NH];        // pre-rounded x (tf32-in-f32)
__device__ float g_hbuf[(size_t)NSLOT * NI];
__device__ float g_obuf[(size_t)NSLOT * NH];

// ---------------- helpers ----------------
__device__ __forceinline__ float rna(float x){
    uint32_t r; asm("cvt.rna.tf32.f32 %0, %1;" : "=r"(r) : "f"(x));
    return __uint_as_float(r);
}
__device__ __forceinline__ uint32_t smem_u32(const void* p){
    uint32_t a;
    asm("{ .reg .u64 t; cvta.to.shared.u64 t, %1; cvt.u32.u64 %0, t; }" : "=r"(a) : "l"(p));
    return a;
}
__device__ __forceinline__ void cp16(uint32_t dst, const void* src){
    asm volatile("cp.async.cg.shared.global [%0], [%1], 16;" :: "r"(dst), "l"(src) : "memory");
}
__device__ __forceinline__ void cp_commit(){ asm volatile("cp.async.commit_group;" ::: "memory"); }
__device__ __forceinline__ void cp_wait0(){ asm volatile("cp.async.wait_group 0;" ::: "memory"); }

__device__ __forceinline__ void mma_tf32(float d[4], const uint32_t a[4], const uint32_t b[2]){
    asm volatile("mma.sync.aligned.m16n8k8.row.col.f32.tf32.tf32.f32 "
        "{%0,%1,%2,%3},{%4,%5,%6,%7},{%8,%9},{%0,%1,%2,%3};"
        : "+f"(d[0]),"+f"(d[1]),"+f"(d[2]),"+f"(d[3])
        : "r"(a[0]),"r"(a[1]),"r"(a[2]),"r"(a[3]),"r"(b[0]),"r"(b[1]));
}
__device__ __forceinline__ float act_fn(float g, float u){
    g = fminf(g, FLIMIT);
    u = fminf(fmaxf(u, -FLIMIT), FLIMIT);
    float sig = __fdividef(1.f, 1.f + __expf(-ALPHA*g));
    return (u + 1.f) * (g * sig);
}

// ---------------- K0: pre-round x to tf32 ----------------
__global__ void prep_x_kernel(const float* __restrict__ x)
{
    const int i = blockIdx.x * blockDim.x + threadIdx.x;  // float4 index
    float4 v = *(const float4*)(x + (size_t)i*4);
    v.x = rna(v.x); v.y = rna(v.y); v.z = rna(v.z); v.w = rna(v.w);
    *(float4*)(g_xr + (size_t)i*4) = v;
}

// ---------------- K1: router ----------------
__global__ void router_kernel(const float* __restrict__ x,
                              const float* __restrict__ rw,
                              const float* __restrict__ rb)
{
    __shared__ float sx[NH];
    __shared__ float slog[NEXP];
    const int t = blockIdx.x;
    for (int i = threadIdx.x; i < NH; i += blockDim.x)
        sx[i] = x[(size_t)t*NH + i];
    __syncthreads();
    const int w = threadIdx.x >> 5;
    const int lane = threadIdx.x & 31;
    const float* wr = rw + (size_t)w*NH;
    float s = 0.f;
    for (int i = lane; i < NH; i += 32) s += sx[i]*wr[i];
    #pragma unroll
    for (int o=16;o>0;o>>=1) s += __shfl_xor_sync(0xffffffffu, s, o);
    if (lane==0) slog[w] = s + rb[w];
    __syncthreads();
    if (threadIdx.x==0){
        float v[NEXP];
        #pragma unroll
        for (int e=0;e<NEXP;e++) v[e]=slog[e];
        int idx[NTOP]; float val[NTOP];
        #pragma unroll
        for (int k=0;k<NTOP;k++){
            int bi=0; float bv=v[0];
            #pragma unroll
            for (int e=1;e<NEXP;e++){ if (v[e]>bv){bv=v[e];bi=e;} }
            idx[k]=bi; val[k]=bv; v[bi]=-3.4e38f;
        }
        float mx=val[0], ssum=0.f, ev[NTOP];
        #pragma unroll
        for(int k=0;k<NTOP;k++){ ev[k]=expf(val[k]-mx); ssum+=ev[k]; }
        float inv = 1.f/ssum;
        #pragma unroll
        for(int k=0;k<NTOP;k++){
            g_tok_exp[t*NTOP+k]=idx[k];
            g_tok_w[t*NTOP+k]=ev[k]*inv;
        }
    }
}

// ---------------- K2: build per-expert token lists ----------------
__global__ void build_lists_kernel()
{
    __shared__ int sc[NEXP], so[NEXP], scur[NEXP];
    const int t = threadIdx.x;
    if (t < NEXP) sc[t]=0;
    __syncthreads();
    int ex[NTOP];
    #pragma unroll
    for (int k=0;k<NTOP;k++){ ex[k]=g_tok_exp[t*NTOP+k]; atomicAdd(&sc[ex[k]],1); }
    __syncthreads();
    if (t==0){
        int acc=0;
        for(int e=0;e<NEXP;e++){ so[e]=acc; acc+=sc[e]; }
    }
    __syncthreads();
    if (t<NEXP){ g_counts[t]=sc[t]; g_offsets[t]=so[t]; scur[t]=so[t]; }
    __syncthreads();
    #pragma unroll
    for (int k=0;k<NTOP;k++){
        int slot = atomicAdd(&scur[ex[k]],1);
        g_token_list[slot]=t;
        g_slot_of[t*NTOP+k]=slot;
    }
}

// ---------------- K3: gate+up GEMM (tf32 mma.sync) + activation ----------------
// CTA: 512 thr, BM=256 tokens, 64 I-cols (gate) + 64 (up). BK=32, double-buffered.
// Warps: wm = (wid&3)*64, wn = (wid>>2)*32 (wn<64 -> gate, else up).
__global__ void __launch_bounds__(512,1)
gateup_kernel(const float* __restrict__ gblk, const float* __restrict__ gscl,
              const float* __restrict__ gbia,
              const float* __restrict__ ublk, const float* __restrict__ uscl,
              const float* __restrict__ ubia)
{
    extern __shared__ float sm[];
    __shared__ int sTok[256];
    __shared__ float sGb[64], sUb[64];

    const int e   = blockIdx.y >> 2;
    const int mt  = blockIdx.y & 3;
    const int M   = g_counts[e];
    if (mt*256 >= M) return;
    const int Mrows = min(256, M - mt*256);
    const int off = g_offsets[e];
    const int n0  = blockIdx.x * 64;
    const int tid = threadIdx.x;
    const int wid = tid >> 5;
    const int lane = tid & 31;

    if (tid < 256){
        int ml = mt*256 + tid; if (ml > M-1) ml = M-1;
        sTok[tid] = g_token_list[off + ml];
    }
    if (tid < 64){
        sGb[tid] = gbia[(size_t)e*NI + n0 + tid];
        sUb[tid] = ubia[(size_t)e*NI + n0 + tid];
    }
    __syncthreads();

    // A staging: 4 cp.async per thread
    const float* srcA[4]; uint32_t dstA[4];
    const uint32_t smemBase = smem_u32(sm);
    #pragma unroll
    for (int j=0;j<4;j++){
        int id = tid + 512*j;
        int r = id>>3, s = id&7;
        srcA[j] = g_xr + (size_t)sTok[r]*NH + s*4;
        dstA[j] = smemBase + (uint32_t)(r*STRB + s*16);
    }
    // B staging: rows 0-63 gate, 64-127 up; 2 float4 per thread
    const float* pB[2]; const float* pS[2]; uint32_t oB[2];
    #pragma unroll
    for (int j=0;j<2;j++){
        int id = tid + 512*j;
        int r = id>>3, s = id&7;
        size_t grow;
        const float *blk, *scl;
        if (r < 64){ grow = (size_t)e*NI + (n0 + r);      blk = gblk; scl = gscl; }
        else       { grow = (size_t)e*NI + (n0 + r - 64); blk = ublk; scl = uscl; }
        pB[j] = blk + grow*NH + s*4;
        pS[j] = scl + grow*NBLKS;
        oB[j] = (uint32_t)(A_WORDS + r*STRW + s*4);
    }

    const int wm = (wid & 3) * 64;
    const int wn = (wid >> 2) * 32;
    const int fr = lane >> 2;
    const int fc = lane & 3;
    const bool active = (wm < Mrows);

    float acc[4][4][4];
    #pragma unroll
    for (int a=0;a<4;a++)
        #pragma unroll
        for (int b=0;b<4;b++)
            #pragma unroll
            for (int c=0;c<4;c++) acc[a][b][c]=0.f;

    // prologue: stage chunk 0 into buf 0
    {
        #pragma unroll
        for (int j=0;j<4;j++) cp16(dstA[j], srcA[j]);
        cp_commit();
        #pragma unroll
        for (int j=0;j<2;j++){
            float4 v = *(const float4*)(pB[j]);
            float s = pS[j][0];
            float* d = sm + oB[j];
            d[0]=rna(v.x*s); d[1]=rna(v.y*s); d[2]=rna(v.z*s); d[3]=rna(v.w*s);
        }
        cp_wait0();
    }
    __syncthreads();

    for (int kc=0; kc<NCHUNK; kc++){
        const int buf = kc & 1;
        const int nb  = buf ^ 1;
        const bool more = (kc+1 < NCHUNK);
        float4 vB[2]; float sB[2];
        if (more){
            const int koff = (kc+1)*32;
            #pragma unroll
            for (int j=0;j<4;j++) cp16(dstA[j] + nb*(STAGE_WORDS*4), srcA[j] + koff);
            cp_commit();
            #pragma unroll
            for (int j=0;j<2;j++){ vB[j] = *(const float4*)(pB[j] + koff); sB[j] = pS[j][kc+1]; }
        }
        if (active){
            const float* Ab = sm + buf*STAGE_WORDS;
            const float* Bb = Ab + A_WORDS;
            #pragma unroll
            for (int ks=0; ks<4; ks++){
                const int kk = ks*8 + fc;
                uint32_t af[4][4];
                #pragma unroll
                for (int m2=0;m2<4;m2++){
                    const int r = wm + m2*16 + fr;
                    af[m2][0] = __float_as_uint(Ab[r*STRW + kk]);
                    af[m2][1] = __float_as_uint(Ab[(r+8)*STRW + kk]);
                    af[m2][2] = __float_as_uint(Ab[r*STRW + kk+4]);
                    af[m2][3] = __float_as_uint(Ab[(r+8)*STRW + kk+4]);
                }
                #pragma unroll
                for (int nt=0; nt<4; nt++){
                    const int c = wn + nt*8 + fr;
                    uint32_t b2[2] = {__float_as_uint(Bb[c*STRW + kk]),
                                      __float_as_uint(Bb[c*STRW + kk+4])};
                    #pragma unroll
                    for (int m2=0;m2<4;m2++) mma_tf32(acc[m2][nt], af[m2], b2);
                }
            }
        }
        if (more){
            #pragma unroll
            for (int j=0;j<2;j++){
                float* d = sm + nb*STAGE_WORDS + oB[j];
                d[0]=rna(vB[j].x*sB[j]); d[1]=rna(vB[j].y*sB[j]);
                d[2]=rna(vB[j].z*sB[j]); d[3]=rna(vB[j].w*sB[j]);
            }
            cp_wait0();
        }
        __syncthreads();
    }

    // epilogue: gate warps stash raw acc to smem G [256][72], up warps combine.
    float* G = sm;   // 256*72*4 = 73728 B, fits in dyn smem
    if (wn < 64 && active){
        #pragma unroll
        for (int m2=0;m2<4;m2++){
            #pragma unroll
            for (int nt=0;nt<4;nt++){
                const int rl = wm + m2*16 + fr;
                const int c  = wn + nt*8 + fc*2;
                *(float2*)&G[rl*72 + c]     = make_float2(acc[m2][nt][0], acc[m2][nt][1]);
                *(float2*)&G[(rl+8)*72 + c] = make_float2(acc[m2][nt][2], acc[m2][nt][3]);
            }
        }
    }
    __syncthreads();
    if (wn >= 64 && active){
        #pragma unroll
        for (int m2=0;m2<4;m2++){
            #pragma unroll
            for (int nt=0;nt<4;nt++){
                const int rl = wm + m2*16 + fr;
                const int cu = (wn-64) + nt*8 + fc*2;
                const float gb0 = sGb[cu], gb1 = sGb[cu+1];
                const float ub0 = sUb[cu], ub1 = sUb[cu+1];
                if (rl < Mrows){
                    float2 gp = *(float2*)&G[rl*72 + cu];
                    float h0 = rna(act_fn(gp.x+gb0, acc[m2][nt][0]+ub0));
                    float h1 = rna(act_fn(gp.y+gb1, acc[m2][nt][1]+ub1));
                    *(float2*)&g_hbuf[(size_t)(off + mt*256 + rl)*NI + n0 + cu] = make_float2(h0,h1);
                }
                if (rl+8 < Mrows){
                    float2 gp = *(float2*)&G[(rl+8)*72 + cu];
                    float h0 = rna(act_fn(gp.x+gb0, acc[m2][nt][2]+ub0));
                    float h1 = rna(act_fn(gp.y+gb1, acc[m2][nt][3]+ub1));
                    *(float2*)&g_hbuf[(size_t)(off + mt*256 + rl+8)*NI + n0 + cu] = make_float2(h0,h1);
                }
            }
        }
    }
}

// ---------------- K4: down GEMM + bias ----------------
// CTA: 512 thr, BM=256 slots, BN=128 H-cols, BK=32, double-buffered.
__global__ void __launch_bounds__(512,1)
down_kernel(const float* __restrict__ dblk, const float* __restrict__ dscl,
            const float* __restrict__ dbia)
{
    extern __shared__ float sm[];
    __shared__ int sRow[256];
    __shared__ float sDb[128];

    const int e   = blockIdx.y >> 2;
    const int mt  = blockIdx.y & 3;
    const int M   = g_counts[e];
    if (mt*256 >= M) return;
    const int Mrows = min(256, M - mt*256);
    const int off = g_offsets[e];
    const int n0  = blockIdx.x * 128;
    const int tid = threadIdx.x;
    const int wid = tid >> 5;
    const int lane = tid & 31;

    if (tid < 256){
        int ml = mt*256 + tid; if (ml > M-1) ml = M-1;
        sRow[tid] = off + ml;
    }
    if (tid < 128) sDb[tid] = dbia[(size_t)e*NH + n0 + tid];
    __syncthreads();

    const float* srcA[4]; uint32_t dstA[4];
    const uint32_t smemBase = smem_u32(sm);
    #pragma unroll
    for (int j=0;j<4;j++){
        int id = tid + 512*j;
        int r = id>>3, s = id&7;
        srcA[j] = g_hbuf + (size_t)sRow[r]*NI + s*4;
        dstA[j] = smemBase + (uint32_t)(r*STRB + s*16);
    }
    const float* pB[2]; const float* pS[2]; uint32_t oB[2];
    #pragma unroll
    for (int j=0;j<2;j++){
        int id = tid + 512*j;
        int r = id>>3, s = id&7;
        size_t grow = (size_t)e*NH + (n0 + r);
        pB[j] = dblk + grow*NI + s*4;
        pS[j] = dscl + grow*NBLKS;
        oB[j] = (uint32_t)(A_WORDS + r*STRW + s*4);
    }

    const int wm = (wid & 3) * 64;
    const int wn = (wid >> 2) * 32;
    const int fr = lane >> 2;
    const int fc = lane & 3;
    const bool active = (wm < Mrows);

    float acc[4][4][4];
    #pragma unroll
    for (int a=0;a<4;a++)
        #pragma unroll
        for (int b=0;b<4;b++)
            #pragma unroll
            for (int c=0;c<4;c++) acc[a][b][c]=0.f;

    {
        #pragma unroll
        for (int j=0;j<4;j++) cp16(dstA[j], srcA[j]);
        cp_commit();
        #pragma unroll
        for (int j=0;j<2;j++){
            float4 v = *(const float4*)(pB[j]);
            float s = pS[j][0];
            float* d = sm + oB[j];
            d[0]=rna(v.x*s); d[1]=rna(v.y*s); d[2]=rna(v.z*s); d[3]=rna(v.w*s);
        }
        cp_wait0();
    }
    __syncthreads();

    for (int kc=0; kc<NCHUNK; kc++){
        const int buf = kc & 1;
        const int nb  = buf ^ 1;
        const bool more = (kc+1 < NCHUNK);
        float4 vB[2]; float sB[2];
        if (more){
            const int koff = (kc+1)*32;
            #pragma unroll
            for (int j=0;j<4;j++) cp16(dstA[j] + nb*(STAGE_WORDS*4), srcA[j] + koff);
            cp_commit();
            #pragma unroll
            for (int j=0;j<2;j++){ vB[j] = *(const float4*)(pB[j] + koff); sB[j] = pS[j][kc+1]; }
        }
        if (active){
            const float* Ab = sm + buf*STAGE_WORDS;
            const float* Bb = Ab + A_WORDS;
            #pragma unroll
            for (int ks=0; ks<4; ks++){
                const int kk = ks*8 + fc;
                uint32_t af[4][4];
                #pragma unroll
                for (int m2=0;m2<4;m2++){
                    const int r = wm + m2*16 + fr;
                    af[m2][0] = __float_as_uint(Ab[r*STRW + kk]);
                    af[m2][1] = __float_as_uint(Ab[(r+8)*STRW + kk]);
                    af[m2][2] = __float_as_uint(Ab[r*STRW + kk+4]);
                    af[m2][3] = __float_as_uint(Ab[(r+8)*STRW + kk+4]);
                }
                #pragma unroll
                for (int nt=0; nt<4; nt++){
                    const int c = wn + nt*8 + fr;
                    uint32_t b2[2] = {__float_as_uint(Bb[c*STRW + kk]),
                                      __float_as_uint(Bb[c*STRW + kk+4])};
                    #pragma unroll
                    for (int m2=0;m2<4;m2++) mma_tf32(acc[m2][nt], af[m2], b2);
                }
            }
        }
        if (more){
            #pragma unroll
            for (int j=0;j<2;j++){
                float* d = sm + nb*STAGE_WORDS + oB[j];
                d[0]=rna(vB[j].x*sB[j]); d[1]=rna(vB[j].y*sB[j]);
                d[2]=rna(vB[j].z*sB[j]); d[3]=rna(vB[j].w*sB[j]);
            }
            cp_wait0();
        }
        __syncthreads();
    }

    if (active){
        #pragma unroll
        for (int m2=0;m2<4;m2++){
            #pragma unroll
            for (int nt=0;nt<4;nt++){
                const int rl = wm + m2*16 + fr;
                const int cg = wn + nt*8 + fc*2;
                const float b0 = sDb[cg], b1 = sDb[cg+1];
                if (rl < Mrows){
                    *(float2*)&g_obuf[(size_t)(off + mt*256 + rl)*NH + n0 + cg] =
                        make_float2(acc[m2][nt][0]+b0, acc[m2][nt][1]+b1);
                }
                if (rl+8 < Mrows){
                    *(float2*)&g_obuf[(size_t)(off + mt*256 + rl+8)*NH + n0 + cg] =
                        make_float2(acc[m2][nt][2]+b0, acc[m2][nt][3]+b1);
                }
            }
        }
    }
}

// ---------------- K5: weighted combine ----------------
__global__ void combine_kernel(float* __restrict__ out)
{
    const int t = blockIdx.x;
    int sl[NTOP]; float w[NTOP];
    #pragma unroll
    for (int k=0;k<NTOP;k++){ sl[k]=g_slot_of[t*NTOP+k]; w[k]=g_tok_w[t*NTOP+k]; }
    for (int i = threadIdx.x; i < NH/4; i += blockDim.x){
        float4 a = make_float4(0.f,0.f,0.f,0.f);
        #pragma unroll
        for (int k=0;k<NTOP;k++){
            float4 v = *(const float4*)&g_obuf[(size_t)sl[k]*NH + i*4];
            a.x += w[k]*v.x; a.y += w[k]*v.y; a.z += w[k]*v.z; a.w += w[k]*v.w;
        }
        *(float4*)&out[(size_t)t*NH + i*4] = a;
    }
}

// ---------------- launch ----------------
extern "C" void kernel_launch(void* const* d_in, const int* in_sizes, int n_in,
                              void* d_out, int out_size)
{
    const float* x    = (const float*)d_in[0];
    const float* rw   = (const float*)d_in[1];
    const float* rb   = (const float*)d_in[2];
    const float* gblk = (const float*)d_in[3];
    const float* gscl = (const float*)d_in[4];
    const float* gbia = (const float*)d_in[5];
    const float* ublk = (const float*)d_in[6];
    const float* uscl = (const float*)d_in[7];
    const float* ubia = (const float*)d_in[8];
    const float* dblk = (const float*)d_in[9];
    const float* dscl = (const float*)d_in[10];
    const float* dbia = (const float*)d_in[11];
    float* out = (float*)d_out;

    cudaFuncSetAttribute(gateup_kernel, cudaFuncAttributeMaxDynamicSharedMemorySize, DSMEM_BYTES);
    cudaFuncSetAttribute(down_kernel,   cudaFuncAttributeMaxDynamicSharedMemorySize, DSMEM_BYTES);

    prep_x_kernel<<<(NT*NH/4)/256, 256>>>(x);
    router_kernel<<<NT, 512>>>(x, rw, rb);
    build_lists_kernel<<<1, NT>>>();
    gateup_kernel<<<dim3(NI/64, NEXP*4), 512, DSMEM_BYTES>>>(gblk, gscl, gbia, ublk, uscl, ubia);
    down_kernel<<<dim3(NH/128, NEXP*4), 512, DSMEM_BYTES>>>(dblk, dscl, dbia);
    combine_kernel<<<NT, 256>>>(out);
}